// round 17
// baseline (speedup 1.0000x reference)
#include <cuda_runtime.h>
#include <cstdint>

#define BB 4
#define QQ 1024
#define KKEYS 2048
#define NB 16
#define VD 512
#define CHUNK 256
#define ROWS 8            // rows per K1 block: 4 packed row-pairs
#define NCH 4             // chunks per K1 block (key-split: 1024 keys)
#define NROWS (BB * QQ)
#define CAP 256
#define TAU 2e-7f

typedef unsigned long long ull;
#define SGN2   0x8000000080000000ULL
#define ONES2  0x3F8000003F800000ULL
#define SC2    0x4380000043800000ULL   // (256.0f, 256.0f) exact 2^8 scale

static __device__ __forceinline__ ull pk2(float a, float b) {
    ull r; asm("mov.b64 %0,{%1,%2};" : "=l"(r) : "f"(a), "f"(b)); return r;
}
static __device__ __forceinline__ void upk2(ull v, float& a, float& b) {
    asm("mov.b64 {%0,%1},%2;" : "=f"(a), "=f"(b) : "l"(v));
}
static __device__ __forceinline__ ull add2(ull a, ull b) {
    ull r; asm("add.rn.f32x2 %0,%1,%2;" : "=l"(r) : "l"(a), "l"(b)); return r;
}
static __device__ __forceinline__ ull mul2(ull a, ull b) {
    ull r; asm("mul.rn.f32x2 %0,%1,%2;" : "=l"(r) : "l"(a), "l"(b)); return r;
}

// Per-(row, key-half) partial sums. Each slot is WRITTEN by exactly one K1
// block every call (no accumulation -> no zero-init kernel needed).
__device__ float g_part[NROWS * 2];

// ---------------------------------------------------------------------------
// K1: producer. Block = 8 rows x 1024 keys; grid 1024. Writes raw
// r10 = (256 p)^10 into W; writes per-(row,half) sums to g_part (plain STG).
// ---------------------------------------------------------------------------
__global__ void __launch_bounds__(256, 4) prod10_kernel(
    const float* __restrict__ qbits,
    const float* __restrict__ kbits,
    const int*   __restrict__ mask,
    float*       __restrict__ W)
{
    __shared__ float skey[CHUNK * 20];     // pad 20 -> conflict-free LDS.128
    __shared__ int   smask[CHUNK];
    __shared__ ull   sqn[4][NB];           // packed negated q bits per pair
    __shared__ float spart[4][2][2];       // [pair][h][row-in-pair]

    const int tid = threadIdx.x;
    const int w   = tid >> 5;              // warp 0..7
    const int kx  = tid & 31;
    const int p   = w >> 1;                // row-pair 0..3
    const int h   = w & 1;                 // key half within chunk
    const int bid = blockIdx.x;
    const int kh  = bid & 1;               // key half of the row
    const int qt  = (bid >> 1) & 127;
    const int b   = bid >> 8;
    const int rowbase = b * QQ + qt * ROWS;
    const int rowA = rowbase + 2 * p;
    const int rowB = rowA + 1;

    if (tid < 4 * NB) {                    // packed negated query bits
        int pp = tid >> 4, bit = tid & 15;
        int rA = rowbase + 2 * pp;
        float qa = qbits[(size_t)rA * NB + bit];
        float qc = qbits[(size_t)(rA + 1) * NB + bit];
        sqn[pp][bit] = pk2(-qa, -qc);
    }

    float* wrA = W + (size_t)rowA * KKEYS;
    float* wrB = W + (size_t)rowB * KKEYS;
    const float4* kbase4 = (const float4*)(kbits + (size_t)b * KKEYS * NB);
    const int*    mbase  = mask + b * KKEYS;

    ull s2 = 0ULL;                         // packed partial sums (rowA,rowB)
    for (int c = 0; c < NCH; c++) {
        const int cg = kh * NCH + c;       // global chunk 0..7
#pragma unroll
        for (int it = 0; it < 4; it++) {   // stage 256 keys x 16 floats
            int i = tid + it * 256;
            int k = i >> 2, j = i & 3;
            float4 v = kbase4[(size_t)(cg * CHUNK + k) * 4 + j];
            *(float4*)&skey[k * 20 + j * 4] = v;
        }
        if (tid < CHUNK) smask[tid] = mbase[cg * CHUNK + tid];
        __syncthreads();

        ull prod[4];
#pragma unroll 1
        for (int g = 0; g < 4; g++) {      // bit-group outer: few live q-regs
            const ull q0 = sqn[p][g * 4 + 0];
            const ull q1 = sqn[p][g * 4 + 1];
            const ull q2 = sqn[p][g * 4 + 2];
            const ull q3 = sqn[p][g * 4 + 3];
#pragma unroll
            for (int j = 0; j < 4; j++) {
                const int kl = h * 128 + j * 32 + kx;
                float4 kv = *(const float4*)&skey[kl * 20 + g * 4];
                // t = 1 - |q-k| = 1 + ((k-q) | signbit)
                ull t0 = add2(ONES2, add2(q0, pk2(kv.x, kv.x)) | SGN2);
                ull t1 = add2(ONES2, add2(q1, pk2(kv.y, kv.y)) | SGN2);
                ull t2 = add2(ONES2, add2(q2, pk2(kv.z, kv.z)) | SGN2);
                ull t3 = add2(ONES2, add2(q3, pk2(kv.w, kv.w)) | SGN2);
                ull m  = mul2(mul2(t0, t1), mul2(t2, t3));
                prod[j] = (g == 0) ? m : mul2(prod[j], m);
            }
        }
#pragma unroll
        for (int j = 0; j < 4; j++) {
            const int kl = h * 128 + j * 32 + kx;
            // r10 = (256*p)^10  (exact 2^80 scale; max-free normalization)
            ull r   = mul2(prod[j], SC2);
            ull r2  = mul2(r, r);
            ull r4  = mul2(r2, r2);
            ull r8  = mul2(r4, r4);
            ull r10 = mul2(r8, r2);
            float ra, rb; upk2(r10, ra, rb);
            if (smask[kl] == 0) { ra = 0.0f; rb = 0.0f; }
            const int kg = cg * CHUNK + kl;
            wrA[kg] = ra;
            wrB[kg] = rb;
            s2 = add2(s2, pk2(ra, rb));
        }
        __syncthreads();
    }

    // combine the two h-warps' partials per row in smem, then ONE plain STG
    float sA, sB; upk2(s2, sA, sB);
#pragma unroll
    for (int off = 16; off; off >>= 1) {
        sA += __shfl_xor_sync(0xffffffffu, sA, off);
        sB += __shfl_xor_sync(0xffffffffu, sB, off);
    }
    if (kx == 0) { spart[p][h][0] = sA; spart[p][h][1] = sB; }
    __syncthreads();
    if (tid < 8) {
        int pp = tid >> 1, rp = tid & 1;
        float s = spart[pp][0][rp] + spart[pp][1][rp];
        g_part[(rowbase + 2 * pp + rp) * 2 + kh] = s;
    }
}

// ---------------------------------------------------------------------------
// K2: consumer, one block per row. Uses g_part (no block reduction). Gather
// loop unrolled x4 over a zero-pre-padded compaction list -> 4 concurrent
// LDGs instead of a serial dependent chain.
// ---------------------------------------------------------------------------
__global__ void __launch_bounds__(256, 8) norm_gemv_kernel(
    float*       __restrict__ W,
    const float* __restrict__ vals,
    float*       __restrict__ Out)
{
    __shared__ float sw[CAP + 4];
    __shared__ int   sidx[CAP + 4];
    __shared__ int   scnt;

    const int row = blockIdx.x;
    const int b   = row >> 10;
    const int tid = threadIdx.x;
    float4* wr4 = (float4*)(W + (size_t)row * KKEYS);

    // zero-init list (implicit zero padding past S) + counter
    sw[tid] = 0.0f;
    sidx[tid] = 0;
    if (tid < 4) { sw[CAP + tid] = 0.0f; sidx[CAP + tid] = 0; }
    if (tid == 0) scnt = 0;

    // issue loads early: latency hides under the barrier
    float4 v0 = wr4[tid];
    float4 v1 = wr4[tid + 256];
    const float invs = 1.0f / (g_part[2 * row] + g_part[2 * row + 1]);
    __syncthreads();                       // init visible; loads in flight

    // normalize + write back + compact (S ~ 7 -> few smem atomics)
    v0.x *= invs; v0.y *= invs; v0.z *= invs; v0.w *= invs;
    v1.x *= invs; v1.y *= invs; v1.z *= invs; v1.w *= invs;
    wr4[tid]       = v0;
    wr4[tid + 256] = v1;
    {
        float e[8] = {v0.x, v0.y, v0.z, v0.w, v1.x, v1.y, v1.z, v1.w};
#pragma unroll
        for (int q = 0; q < 8; q++) {
            if (e[q] > TAU) {
                int pos = atomicAdd(&scnt, 1);
                int k = (q < 4) ? (tid * 4 + q) : ((tid + 256) * 4 + q - 4);
                if (pos < CAP) { sw[pos] = e[q]; sidx[pos] = k; }
            }
        }
    }
    __syncthreads();

    const int S = scnt;
    const float* V = vals + (size_t)b * KKEYS * VD;

    float ax0 = 0.f, ay0 = 0.f, ax1 = 0.f, ay1 = 0.f;
    float ax2 = 0.f, ay2 = 0.f, ax3 = 0.f, ay3 = 0.f;

    if (S <= CAP) {
        const int S4 = (S + 3) & ~3;       // zero-padded to here
        for (int s = 0; s < S4; s += 4) {
            float w0 = sw[s],     w1 = sw[s + 1];
            float w2 = sw[s + 2], w3 = sw[s + 3];
            const float2 u0 = ((const float2*)(V + (size_t)sidx[s]     * VD))[tid];
            const float2 u1 = ((const float2*)(V + (size_t)sidx[s + 1] * VD))[tid];
            const float2 u2 = ((const float2*)(V + (size_t)sidx[s + 2] * VD))[tid];
            const float2 u3 = ((const float2*)(V + (size_t)sidx[s + 3] * VD))[tid];
            ax0 = fmaf(w0, u0.x, ax0); ay0 = fmaf(w0, u0.y, ay0);
            ax1 = fmaf(w1, u1.x, ax1); ay1 = fmaf(w1, u1.y, ay1);
            ax2 = fmaf(w2, u2.x, ax2); ay2 = fmaf(w2, u2.y, ay2);
            ax3 = fmaf(w3, u3.x, ax3); ay3 = fmaf(w3, u3.y, ay3);
        }
    } else {
        // dense fallback: W row normalized above (ordered by the barrier)
        const float* wr = W + (size_t)row * KKEYS;
        for (int k = 0; k < KKEYS; k++) {
            float wgt = wr[k];
            if (wgt > TAU) {
                const float2 v = ((const float2*)(V + (size_t)k * VD))[tid];
                ax0 = fmaf(wgt, v.x, ax0);
                ay0 = fmaf(wgt, v.y, ay0);
            }
        }
    }

    float ax = (ax0 + ax1) + (ax2 + ax3);
    float ay = (ay0 + ay1) + (ay2 + ay3);
    ((float2*)(Out + (size_t)row * VD))[tid] = make_float2(ax, ay);
}

// ---------------------------------------------------------------------------
// Launch: out layout = [output (B,Q,V) | weights (B,Q,K)] per reference tuple.
// ---------------------------------------------------------------------------
extern "C" void kernel_launch(void* const* d_in, const int* in_sizes, int n_in,
                              void* d_out, int out_size)
{
    (void)in_sizes; (void)n_in; (void)out_size;
    const float* qb   = (const float*)d_in[0];
    const float* kb   = (const float*)d_in[1];
    const float* vals = (const float*)d_in[2];
    const int*   mask = (const int*)d_in[3];

    float* out = (float*)d_out;
    float* W   = out + (size_t)BB * QQ * VD;   // weights region

    prod10_kernel<<<BB * (QQ / ROWS) * 2, 256>>>(qb, kb, mask, W);
    norm_gemv_kernel<<<NROWS, 256>>>(W, vals, out);
}